// round 1
// baseline (speedup 1.0000x reference)
#include <cuda_runtime.h>

#define B_DIM 1024
#define L_DIM 200
#define E_DIM 128
#define C_DIM 384
#define OUT_D 10000
#define M_DIM (B_DIM * L_DIM)   // 204800

// Scratch (static device allocations are allowed; runtime allocs are not).
__device__ float g_ctx[(size_t)M_DIM * C_DIM];   // 314 MB gathered [se|pe|ee]
__device__ float g_h[(size_t)M_DIM * C_DIM];     // 314 MB tanh(ctx @ W_fc^T)
__device__ float g_cv[B_DIM * C_DIM];            // attention-pooled code vectors

// ---------------------------------------------------------------------------
// Kernel 1: embedding gather -> g_ctx.  One float4 per thread.
// Row m = b*L + l; cols [0,128)=node_emb[starts], [128,256)=path_emb[paths],
// [256,384)=node_emb[ends].
// ---------------------------------------------------------------------------
__global__ __launch_bounds__(256)
void gather_ctx_kernel(const int* __restrict__ starts,
                       const int* __restrict__ paths,
                       const int* __restrict__ ends,
                       const float* __restrict__ node_emb,
                       const float* __restrict__ path_emb) {
    int idx = blockIdx.x * blockDim.x + threadIdx.x;   // < 204800*96 = 19.66M
    int m = idx / 96;
    int q = idx - m * 96;                              // float4 index in row
    float4 v;
    if (q < 32) {
        v = reinterpret_cast<const float4*>(node_emb)[(long)starts[m] * 32 + q];
    } else if (q < 64) {
        v = reinterpret_cast<const float4*>(path_emb)[(long)paths[m] * 32 + (q - 32)];
    } else {
        v = reinterpret_cast<const float4*>(node_emb)[(long)ends[m] * 32 + (q - 64)];
    }
    reinterpret_cast<float4*>(g_ctx)[(long)m * 96 + q] = v;
}

// ---------------------------------------------------------------------------
// Generic fp32 SGEMM: C[m,n] = op( sum_k A[m,k] * Bw[n,k] (+ bias[n]) )
// A: [M,K] row-major, Bw: [N,K] row-major. Tile 128x128x16, 256 threads,
// 8x8 per thread. M and K assumed multiples of 128/16; N guarded.
// ---------------------------------------------------------------------------
template <bool TANH, bool BIAS>
__global__ __launch_bounds__(256)
void sgemm_kernel(const float* __restrict__ A, const float* __restrict__ Bw,
                  const float* __restrict__ bias, float* __restrict__ C,
                  int N, int K) {
    __shared__ float As[16][128];
    __shared__ float Bs[16][128];
    const int tid  = threadIdx.x;
    const int row0 = blockIdx.y * 128;
    const int col0 = blockIdx.x * 128;
    const int tx = tid & 15;        // n direction (8 cols each)
    const int ty = tid >> 4;        // m direction (8 rows each)
    const int lr = tid >> 2;        // load row (0..63), +64 for second half
    const int lc = (tid & 3) * 4;   // load col (float4)

    float acc[8][8];
    #pragma unroll
    for (int i = 0; i < 8; i++)
        #pragma unroll
        for (int j = 0; j < 8; j++) acc[i][j] = 0.f;

    for (int k0 = 0; k0 < K; k0 += 16) {
        #pragma unroll
        for (int h = 0; h < 2; h++) {
            int r = lr + h * 64;
            float4 va = *reinterpret_cast<const float4*>(
                A + (long)(row0 + r) * K + k0 + lc);
            As[lc + 0][r] = va.x; As[lc + 1][r] = va.y;
            As[lc + 2][r] = va.z; As[lc + 3][r] = va.w;

            int n = col0 + r;
            float4 vb = make_float4(0.f, 0.f, 0.f, 0.f);
            if (n < N)
                vb = *reinterpret_cast<const float4*>(
                    Bw + (long)n * K + k0 + lc);
            Bs[lc + 0][r] = vb.x; Bs[lc + 1][r] = vb.y;
            Bs[lc + 2][r] = vb.z; Bs[lc + 3][r] = vb.w;
        }
        __syncthreads();
        #pragma unroll
        for (int k = 0; k < 16; k++) {
            float ra[8], rb[8];
            #pragma unroll
            for (int i = 0; i < 8; i++) ra[i] = As[k][ty * 8 + i];
            #pragma unroll
            for (int j = 0; j < 8; j++) rb[j] = Bs[k][tx * 8 + j];
            #pragma unroll
            for (int i = 0; i < 8; i++)
                #pragma unroll
                for (int j = 0; j < 8; j++)
                    acc[i][j] = fmaf(ra[i], rb[j], acc[i][j]);
        }
        __syncthreads();
    }

    #pragma unroll
    for (int i = 0; i < 8; i++) {
        int m = row0 + ty * 8 + i;
        #pragma unroll
        for (int j = 0; j < 8; j++) {
            int n = col0 + tx * 8 + j;
            if (n < N) {
                float v = acc[i][j];
                if (BIAS) v += bias[n];
                if (TANH) v = tanhf(v);
                C[(long)m * N + n] = v;
            }
        }
    }
}

// ---------------------------------------------------------------------------
// Kernel 3: per-batch attention.  scores = h . a, softmax over L,
// cv[b,c] = sum_l attn[l] * h[b,l,c].  One block per batch element.
// ---------------------------------------------------------------------------
__global__ __launch_bounds__(256)
void attn_kernel(const float* __restrict__ a_vec,
                 const float* __restrict__ h,
                 float* __restrict__ cv) {
    __shared__ float s_a[C_DIM];
    __shared__ float s_sc[L_DIM];
    __shared__ float red[8];
    const int b = blockIdx.x;
    const int tid = threadIdx.x;
    const int lane = tid & 31, warp = tid >> 5;
    const float* hb = h + (long)b * L_DIM * C_DIM;

    for (int c = tid; c < C_DIM; c += 256) s_a[c] = a_vec[c];
    __syncthreads();

    // scores: one warp per row l (round-robin)
    for (int l = warp; l < L_DIM; l += 8) {
        float s = 0.f;
        const float* row = hb + l * C_DIM;
        for (int c = lane; c < C_DIM; c += 32) s = fmaf(row[c], s_a[c], s);
        #pragma unroll
        for (int o = 16; o; o >>= 1) s += __shfl_xor_sync(0xffffffffu, s, o);
        if (lane == 0) s_sc[l] = s;
    }
    __syncthreads();

    // softmax over L=200 (one score per thread, tid<200)
    float v = (tid < L_DIM) ? s_sc[tid] : -1e30f;
    float mx = v;
    #pragma unroll
    for (int o = 16; o; o >>= 1) mx = fmaxf(mx, __shfl_xor_sync(0xffffffffu, mx, o));
    if (lane == 0) red[warp] = mx;
    __syncthreads();
    if (tid == 0) {
        float t = red[0];
        #pragma unroll
        for (int i = 1; i < 8; i++) t = fmaxf(t, red[i]);
        red[0] = t;
    }
    __syncthreads();
    const float gmax = red[0];
    __syncthreads();

    float e = (tid < L_DIM) ? expf(v - gmax) : 0.f;
    float sm = e;
    #pragma unroll
    for (int o = 16; o; o >>= 1) sm += __shfl_xor_sync(0xffffffffu, sm, o);
    if (lane == 0) red[warp] = sm;
    __syncthreads();
    if (tid == 0) {
        float t = 0.f;
        #pragma unroll
        for (int i = 0; i < 8; i++) t += red[i];
        red[0] = t;
    }
    __syncthreads();
    const float inv = 1.0f / red[0];
    if (tid < L_DIM) s_sc[tid] = e * inv;
    __syncthreads();

    // weighted sum over L -> cv
    for (int c = tid; c < C_DIM; c += 256) {
        float acc = 0.f;
        #pragma unroll 4
        for (int l = 0; l < L_DIM; l++)
            acc = fmaf(s_sc[l], hb[l * C_DIM + c], acc);
        cv[b * C_DIM + c] = acc;
    }
}

// ---------------------------------------------------------------------------
extern "C" void kernel_launch(void* const* d_in, const int* in_sizes, int n_in,
                              void* d_out, int out_size) {
    const int*   starts   = (const int*)  d_in[0];
    const int*   paths    = (const int*)  d_in[1];
    const int*   ends     = (const int*)  d_in[2];
    const float* node_emb = (const float*)d_in[3];
    const float* path_emb = (const float*)d_in[4];
    const float* W_fc     = (const float*)d_in[5];
    const float* a_vec    = (const float*)d_in[6];
    const float* W_out    = (const float*)d_in[7];
    const float* b_out    = (const float*)d_in[8];
    float* out = (float*)d_out;

    float *p_ctx, *p_h, *p_cv;
    cudaGetSymbolAddress((void**)&p_ctx, g_ctx);
    cudaGetSymbolAddress((void**)&p_h,   g_h);
    cudaGetSymbolAddress((void**)&p_cv,  g_cv);

    // 1) gather ctx
    gather_ctx_kernel<<<(M_DIM * 96) / 256, 256>>>(starts, paths, ends,
                                                   node_emb, path_emb);
    // 2) h = tanh(ctx @ W_fc^T)   [204800 x 384]
    sgemm_kernel<true, false><<<dim3(C_DIM / 128, M_DIM / 128), 256>>>(
        p_ctx, W_fc, nullptr, p_h, C_DIM, C_DIM);
    // 3) attention pooling -> cv [1024 x 384]
    attn_kernel<<<B_DIM, 256>>>(a_vec, p_h, p_cv);
    // 4) out = cv @ W_out^T + b_out   [1024 x 10000]
    sgemm_kernel<false, true><<<dim3((OUT_D + 127) / 128, B_DIM / 128), 256>>>(
        p_cv, W_out, b_out, out, OUT_D, C_DIM);
}

// round 5
// speedup vs baseline: 3.8093x; 3.8093x over previous
#include <cuda_runtime.h>
#include <cuda_fp16.h>
#include <cstdint>

#define B_DIM 1024
#define L_DIM 200
#define C_DIM 384
#define OUT_D 10000
#define M1    (B_DIM * L_DIM)     // 204800

#define KT  32                    // k-tile
#define LDSX 40                   // smem row stride in halves (conflict-free)

// ---- device scratch (static allocations only) ------------------------------
__device__ __half g_h[(size_t)M1 * C_DIM];          // 157 MB fp16 h
__device__ float  g_cv[B_DIM * C_DIM];              // pooled code vectors
__device__ __half g_wfc[C_DIM * C_DIM];             // W_fc in fp16
__device__ __half g_wout[(size_t)OUT_D * C_DIM];    // W_out in fp16

// ---- helpers ---------------------------------------------------------------
__device__ __forceinline__ void ldsm4(uint32_t (&r)[4], uint32_t saddr) {
    asm volatile("ldmatrix.sync.aligned.m8n8.x4.shared.b16 {%0,%1,%2,%3}, [%4];\n"
                 : "=r"(r[0]), "=r"(r[1]), "=r"(r[2]), "=r"(r[3]) : "r"(saddr));
}

__device__ __forceinline__ void mma16816(float (&c)[4], const uint32_t (&a)[4],
                                         uint32_t b0, uint32_t b1) {
    asm volatile(
        "mma.sync.aligned.m16n8k16.row.col.f32.f16.f16.f32 "
        "{%0,%1,%2,%3}, {%4,%5,%6,%7}, {%8,%9}, {%0,%1,%2,%3};\n"
        : "+f"(c[0]), "+f"(c[1]), "+f"(c[2]), "+f"(c[3])
        : "r"(a[0]), "r"(a[1]), "r"(a[2]), "r"(a[3]), "r"(b0), "r"(b1));
}

// tanh: inputs here have |x| ~ 0.02 (std); polynomial exact to ~1e-9 for
// |x|<=0.25, accurate tanhf fallback for the (never-in-practice) tail.
__device__ __forceinline__ float tanh_fast(float x) {
    float x2 = x * x;
    float p = fmaf(x2, fmaf(x2, 0.133333333f, -0.333333333f), 1.0f);
    float v = x * p;
    if (fabsf(x) > 0.25f) v = tanhf(x);
    return v;
}

// ---- fp32 -> fp16 weight conversion ---------------------------------------
__global__ __launch_bounds__(256)
void f2h_kernel(const float* __restrict__ s, __half* __restrict__ d, int n4) {
    int i = blockIdx.x * blockDim.x + threadIdx.x;
    if (i < n4) {
        float4 f = reinterpret_cast<const float4*>(s)[i];
        __half2 h0 = __floats2half2_rn(f.x, f.y);
        __half2 h1 = __floats2half2_rn(f.z, f.w);
        __half2* dp = reinterpret_cast<__half2*>(d) + 2 * i;
        dp[0] = h0; dp[1] = h1;
    }
}

// ---------------------------------------------------------------------------
// Tensor-core GEMM: C[m,n] = op( sum_k A[m,k] * Bw16[n,k] )
//   GATHER=1: A rows come from embedding tables via (starts,paths,ends),
//             K segments [0,128)=node[start], [128,256)=path, [256,384)=node[end]
//   GATHER=0: A = Adense fp32 [M x 384]
//   TANH=1 : out fp16 = tanh(acc)        (GEMM1)
//   TANH=0 : out fp32 = acc + bias[n]    (GEMM2), with n<Nw guard
// CTA tile 128x128, k-tile 32, 8 warps as 4(m) x 2(n), warp tile 32x64.
// ---------------------------------------------------------------------------
template <int GATHER, int TANH>
__global__ __launch_bounds__(256)
void mma_gemm(const float* __restrict__ Adense,
              const int* __restrict__ starts, const int* __restrict__ paths,
              const int* __restrict__ ends,
              const float* __restrict__ node_emb, const float* __restrict__ path_emb,
              const __half* __restrict__ Bw, const float* __restrict__ bias,
              void* __restrict__ Cout, int Nw) {
    __shared__ __align__(16) __half sA[2][128 * LDSX];
    __shared__ __align__(16) __half sB[2][128 * LDSX];
    const int tid = threadIdx.x;
    const int m0 = blockIdx.y * 128, n0 = blockIdx.x * 128;

    // -------- loader mapping (256 thr: 2 threads per row, 16 halves each)
    const int ar = tid >> 1, aseg = (tid & 1) * 16;
    const int br = ar,       bseg = aseg;
    int i_s = 0, i_p = 0, i_e = 0;
    if (GATHER) { int m = m0 + ar; i_s = starts[m]; i_p = paths[m]; i_e = ends[m]; }

    float4 fA[4];
    uint4  uB[2];

    auto loadA = [&](int k0) {
        const float* ap;
        if (GATHER) {
            int k = k0 + aseg;
            if (k < 128)      ap = node_emb + (size_t)i_s * 128 + k;
            else if (k < 256) ap = path_emb + (size_t)i_p * 128 + (k - 128);
            else              ap = node_emb + (size_t)i_e * 128 + (k - 256);
        } else {
            ap = Adense + (size_t)(m0 + ar) * C_DIM + k0 + aseg;
        }
        #pragma unroll
        for (int q = 0; q < 4; q++) fA[q] = reinterpret_cast<const float4*>(ap)[q];
    };
    auto loadB = [&](int k0) {
        int nr = n0 + br;
        if (nr < Nw) {
            const uint4* bp = reinterpret_cast<const uint4*>(
                Bw + (size_t)nr * C_DIM + k0 + bseg);
            uB[0] = bp[0]; uB[1] = bp[1];
        } else {
            uB[0] = make_uint4(0, 0, 0, 0); uB[1] = make_uint4(0, 0, 0, 0);
        }
    };
    auto storeStage = [&](int buf) {
        __half2 h[8];
        #pragma unroll
        for (int q = 0; q < 4; q++) {
            h[2 * q]     = __floats2half2_rn(fA[q].x, fA[q].y);
            h[2 * q + 1] = __floats2half2_rn(fA[q].z, fA[q].w);
        }
        uint4 ua0 = make_uint4(*(uint32_t*)&h[0], *(uint32_t*)&h[1],
                               *(uint32_t*)&h[2], *(uint32_t*)&h[3]);
        uint4 ua1 = make_uint4(*(uint32_t*)&h[4], *(uint32_t*)&h[5],
                               *(uint32_t*)&h[6], *(uint32_t*)&h[7]);
        uint4* pa = reinterpret_cast<uint4*>(&sA[buf][ar * LDSX + aseg]);
        pa[0] = ua0; pa[1] = ua1;
        uint4* pb = reinterpret_cast<uint4*>(&sB[buf][br * LDSX + bseg]);
        pb[0] = uB[0]; pb[1] = uB[1];
    };

    // -------- compute mapping
    const int lane = tid & 31, warp = tid >> 5;
    const int wm = warp & 3, wn = warp >> 2;       // 4 x 2 warp grid
    const int g = lane >> 2, t4 = lane & 3;
    // ldmatrix per-lane addressing: A tiles (m-rows), B tiles (n-rows)
    const int a_row = (lane & 7) + ((lane >> 3) & 1) * 8;
    const int a_ko  = (lane >> 4) * 8;
    const int b_row = (lane & 7) + ((lane >> 4) & 1) * 8;
    const int b_ko  = ((lane >> 3) & 1) * 8;

    float acc[2][8][4];
    #pragma unroll
    for (int i = 0; i < 2; i++)
        #pragma unroll
        for (int j = 0; j < 8; j++)
            #pragma unroll
            for (int q = 0; q < 4; q++) acc[i][j][q] = 0.f;

    loadA(0); loadB(0); storeStage(0);
    __syncthreads();

    const int KSTEPS = C_DIM / KT;   // 12
    for (int s = 0; s < KSTEPS; ++s) {
        const int buf = s & 1;
        if (s + 1 < KSTEPS) { loadA((s + 1) * KT); loadB((s + 1) * KT); }

        #pragma unroll
        for (int ks = 0; ks < 2; ++ks) {
            const int ko = ks * 16;
            uint32_t af[2][4], bf[4][4];
            #pragma unroll
            for (int i = 0; i < 2; i++) {
                uint32_t ad = (uint32_t)__cvta_generic_to_shared(
                    &sA[buf][(wm * 32 + i * 16 + a_row) * LDSX + ko + a_ko]);
                ldsm4(af[i], ad);
            }
            #pragma unroll
            for (int p = 0; p < 4; p++) {
                uint32_t bd = (uint32_t)__cvta_generic_to_shared(
                    &sB[buf][(wn * 64 + p * 16 + b_row) * LDSX + ko + b_ko]);
                ldsm4(bf[p], bd);
            }
            #pragma unroll
            for (int i = 0; i < 2; i++)
                #pragma unroll
                for (int j = 0; j < 8; j++)
                    mma16816(acc[i][j], af[i],
                             bf[j >> 1][(j & 1) * 2], bf[j >> 1][(j & 1) * 2 + 1]);
        }
        if (s + 1 < KSTEPS) storeStage(buf ^ 1);
        __syncthreads();
    }

    // -------- epilogue
    #pragma unroll
    for (int i = 0; i < 2; i++) {
        #pragma unroll
        for (int j = 0; j < 8; j++) {
            const int r = m0 + wm * 32 + i * 16 + g;
            const int c = n0 + wn * 64 + j * 8 + t4 * 2;
            if (TANH) {
                __half* C = (__half*)Cout;
                float v0 = tanh_fast(acc[i][j][0]);
                float v1 = tanh_fast(acc[i][j][1]);
                float v2 = tanh_fast(acc[i][j][2]);
                float v3 = tanh_fast(acc[i][j][3]);
                *reinterpret_cast<__half2*>(&C[(size_t)r * Nw + c]) =
                    __floats2half2_rn(v0, v1);
                *reinterpret_cast<__half2*>(&C[(size_t)(r + 8) * Nw + c]) =
                    __floats2half2_rn(v2, v3);
            } else {
                float* C = (float*)Cout;
                if (c < Nw)     C[(size_t)r * Nw + c]           = acc[i][j][0] + bias[c];
                if (c + 1 < Nw) C[(size_t)r * Nw + c + 1]       = acc[i][j][1] + bias[c + 1];
                if (c < Nw)     C[(size_t)(r + 8) * Nw + c]     = acc[i][j][2] + bias[c];
                if (c + 1 < Nw) C[(size_t)(r + 8) * Nw + c + 1] = acc[i][j][3] + bias[c + 1];
            }
        }
    }
}

// ---------------------------------------------------------------------------
// Attention: one CTA per batch element. Stage h[b] (200x384 fp16, 150 KB) in
// dynamic smem; compute scores, softmax over L, weighted sum -> g_cv.
// ---------------------------------------------------------------------------
__global__ __launch_bounds__(256)
void attn_kernel(const float* __restrict__ a_vec) {
    extern __shared__ __align__(16) __half sh[];   // L_DIM * C_DIM halves
    __shared__ float s_a[C_DIM];
    __shared__ float s_w[L_DIM];
    __shared__ float red[8];
    const int b = blockIdx.x, tid = threadIdx.x;
    const int lane = tid & 31, warp = tid >> 5;

    {   // stage h tile
        const uint4* src = reinterpret_cast<const uint4*>(g_h + (size_t)b * L_DIM * C_DIM);
        uint4* dst = reinterpret_cast<uint4*>(sh);
        for (int i = tid; i < L_DIM * C_DIM / 8; i += 256) dst[i] = src[i];
    }
    for (int c = tid; c < C_DIM; c += 256) s_a[c] = a_vec[c];
    __syncthreads();

    const __half2* sh2 = reinterpret_cast<const __half2*>(sh);

    // scores: one warp per l row-robin
    for (int l = warp; l < L_DIM; l += 8) {
        float s = 0.f;
        for (int c2 = lane; c2 < C_DIM / 2; c2 += 32) {
            float2 f = __half22float2(sh2[l * (C_DIM / 2) + c2]);
            s = fmaf(f.x, s_a[2 * c2], s);
            s = fmaf(f.y, s_a[2 * c2 + 1], s);
        }
        #pragma unroll
        for (int o = 16; o; o >>= 1) s += __shfl_xor_sync(0xffffffffu, s, o);
        if (lane == 0) s_w[l] = s;
    }
    __syncthreads();

    // softmax over L
    float v = (tid < L_DIM) ? s_w[tid] : -1e30f;
    float mx = v;
    #pragma unroll
    for (int o = 16; o; o >>= 1) mx = fmaxf(mx, __shfl_xor_sync(0xffffffffu, mx, o));
    if (lane == 0) red[warp] = mx;
    __syncthreads();
    if (tid == 0) {
        float t = red[0];
        #pragma unroll
        for (int i = 1; i < 8; i++) t = fmaxf(t, red[i]);
        red[0] = t;
    }
    __syncthreads();
    const float gmax = red[0];
    __syncthreads();
    float e = (tid < L_DIM) ? expf(v - gmax) : 0.f;
    float sm = e;
    #pragma unroll
    for (int o = 16; o; o >>= 1) sm += __shfl_xor_sync(0xffffffffu, sm, o);
    if (lane == 0) red[warp] = sm;
    __syncthreads();
    if (tid == 0) {
        float t = 0.f;
        #pragma unroll
        for (int i = 0; i < 8; i++) t += red[i];
        red[0] = t;
    }
    __syncthreads();
    const float inv = 1.0f / red[0];
    if (tid < L_DIM) s_w[tid] = e * inv;
    __syncthreads();

    // weighted sum over L -> cv (threads 0..191 handle half2 columns)
    if (tid < C_DIM / 2) {
        float ax = 0.f, ay = 0.f;
        #pragma unroll 4
        for (int l = 0; l < L_DIM; l++) {
            float w = s_w[l];
            float2 f = __half22float2(sh2[l * (C_DIM / 2) + tid]);
            ax = fmaf(w, f.x, ax);
            ay = fmaf(w, f.y, ay);
        }
        float2 o2 = make_float2(ax, ay);
        *reinterpret_cast<float2*>(&g_cv[b * C_DIM + 2 * tid]) = o2;
    }
}

// ---------------------------------------------------------------------------
extern "C" void kernel_launch(void* const* d_in, const int* in_sizes, int n_in,
                              void* d_out, int out_size) {
    const int*   starts   = (const int*)  d_in[0];
    const int*   paths    = (const int*)  d_in[1];
    const int*   ends     = (const int*)  d_in[2];
    const float* node_emb = (const float*)d_in[3];
    const float* path_emb = (const float*)d_in[4];
    const float* W_fc     = (const float*)d_in[5];
    const float* a_vec    = (const float*)d_in[6];
    const float* W_out    = (const float*)d_in[7];
    const float* b_out    = (const float*)d_in[8];

    __half *p_h, *p_wfc, *p_wout;
    float  *p_cv;
    cudaGetSymbolAddress((void**)&p_h,    g_h);
    cudaGetSymbolAddress((void**)&p_cv,   g_cv);
    cudaGetSymbolAddress((void**)&p_wfc,  g_wfc);
    cudaGetSymbolAddress((void**)&p_wout, g_wout);

    // 0) weight conversions to fp16
    f2h_kernel<<<(C_DIM * C_DIM / 4 + 255) / 256, 256>>>(W_fc, p_wfc, C_DIM * C_DIM / 4);
    f2h_kernel<<<(OUT_D * C_DIM / 4 + 255) / 256, 256>>>(W_out, p_wout, OUT_D * C_DIM / 4);

    // 1) h = tanh(gather(ctx) @ W_fc^T)  -> fp16 [204800 x 384]
    mma_gemm<1, 1><<<dim3(C_DIM / 128, M1 / 128), 256>>>(
        nullptr, starts, paths, ends, node_emb, path_emb,
        p_wfc, nullptr, (void*)p_h, C_DIM);

    // 2) attention pooling -> cv fp32 [1024 x 384]
    cudaFuncSetAttribute(attn_kernel, cudaFuncAttributeMaxDynamicSharedMemorySize,
                         L_DIM * C_DIM * (int)sizeof(__half));
    attn_kernel<<<B_DIM, 256, L_DIM * C_DIM * sizeof(__half)>>>(a_vec);

    // 3) out = cv @ W_out^T + b_out  -> fp32 [1024 x 10000]
    mma_gemm<0, 0><<<dim3((OUT_D + 127) / 128, B_DIM / 128), 256>>>(
        p_cv, nullptr, nullptr, nullptr, nullptr, nullptr,
        p_wout, b_out, d_out, OUT_D);
}

// round 6
// speedup vs baseline: 4.4406x; 1.1657x over previous
#include <cuda_runtime.h>
#include <cuda_fp16.h>
#include <cstdint>

#define B_DIM 1024
#define L_DIM 200
#define C_DIM 384
#define OUT_D 10000
#define M1    (B_DIM * L_DIM)     // 204800

#define KT  32                    // k-tile
#define LDSX 40                   // smem row stride in halves (conflict-free)

// ---- device scratch (static allocations only) ------------------------------
__device__ __half g_h[(size_t)M1 * C_DIM];          // 157 MB fp16 h
__device__ float  g_cv[B_DIM * C_DIM];              // pooled code vectors
__device__ __half g_wfc[C_DIM * C_DIM];             // W_fc in fp16
__device__ __half g_wout[(size_t)OUT_D * C_DIM];    // W_out in fp16
__device__ float  g_spart[3 * (size_t)M1];          // per-n-block score partials

// ---- helpers ---------------------------------------------------------------
__device__ __forceinline__ void ldsm4(uint32_t (&r)[4], uint32_t saddr) {
    asm volatile("ldmatrix.sync.aligned.m8n8.x4.shared.b16 {%0,%1,%2,%3}, [%4];\n"
                 : "=r"(r[0]), "=r"(r[1]), "=r"(r[2]), "=r"(r[3]) : "r"(saddr));
}

__device__ __forceinline__ void mma16816(float (&c)[4], const uint32_t (&a)[4],
                                         uint32_t b0, uint32_t b1) {
    asm volatile(
        "mma.sync.aligned.m16n8k16.row.col.f32.f16.f16.f32 "
        "{%0,%1,%2,%3}, {%4,%5,%6,%7}, {%8,%9}, {%0,%1,%2,%3};\n"
        : "+f"(c[0]), "+f"(c[1]), "+f"(c[2]), "+f"(c[3])
        : "r"(a[0]), "r"(a[1]), "r"(a[2]), "r"(a[3]), "r"(b0), "r"(b1));
}

// tanh: inputs here have |x| ~ 0.02 (std); polynomial exact to ~1e-9 for
// |x|<=0.25, accurate tanhf fallback for the (never-in-practice) tail.
__device__ __forceinline__ float tanh_fast(float x) {
    float x2 = x * x;
    float p = fmaf(x2, fmaf(x2, 0.133333333f, -0.333333333f), 1.0f);
    float v = x * p;
    if (fabsf(x) > 0.25f) v = tanhf(x);
    return v;
}

// ---- fp32 -> fp16 weight conversion ---------------------------------------
__global__ __launch_bounds__(256)
void f2h_kernel(const float* __restrict__ s, __half* __restrict__ d, int n4) {
    int i = blockIdx.x * blockDim.x + threadIdx.x;
    if (i < n4) {
        float4 f = reinterpret_cast<const float4*>(s)[i];
        __half2 h0 = __floats2half2_rn(f.x, f.y);
        __half2 h1 = __floats2half2_rn(f.z, f.w);
        __half2* dp = reinterpret_cast<__half2*>(d) + 2 * i;
        dp[0] = h0; dp[1] = h1;
    }
}

// ---------------------------------------------------------------------------
// Tensor-core GEMM: C[m,n] = op( sum_k A[m,k] * Bw16[n,k] )
//   GATHER=1: A rows gathered from embedding tables; TANH=1 also computes
//             per-n-block partial attention scores sum_c tanh(v)*a[c]
//             into g_spart[nb][m]  (deterministic, no atomics).
//   GATHER=0: A = Adense fp32; TANH=0 adds bias, fp32 out, n<Nw guard.
// CTA tile 128x128, k-tile 32, 8 warps as 4(m) x 2(n), warp tile 32x64.
// ---------------------------------------------------------------------------
template <int GATHER, int TANH>
__global__ __launch_bounds__(256)
void mma_gemm(const float* __restrict__ Adense,
              const int* __restrict__ starts, const int* __restrict__ paths,
              const int* __restrict__ ends,
              const float* __restrict__ node_emb, const float* __restrict__ path_emb,
              const __half* __restrict__ Bw, const float* __restrict__ bias,
              const float* __restrict__ a_vec,
              void* __restrict__ Cout, int Nw) {
    __shared__ __align__(16) __half sA[2][128 * LDSX];
    __shared__ __align__(16) __half sB[2][128 * LDSX];
    __shared__ float sAvec[128];
    __shared__ float sScore[2][128];
    const int tid = threadIdx.x;
    const int m0 = blockIdx.y * 128, n0 = blockIdx.x * 128;

    // -------- loader mapping (256 thr: 2 threads per row, 16 halves each)
    const int ar = tid >> 1, aseg = (tid & 1) * 16;
    const int br = ar,       bseg = aseg;
    int i_s = 0, i_p = 0, i_e = 0;
    if (GATHER) { int m = m0 + ar; i_s = starts[m]; i_p = paths[m]; i_e = ends[m]; }

    float4 fA[4];
    uint4  uB[2];

    auto loadA = [&](int k0) {
        const float* ap;
        if (GATHER) {
            int k = k0 + aseg;
            if (k < 128)      ap = node_emb + (size_t)i_s * 128 + k;
            else if (k < 256) ap = path_emb + (size_t)i_p * 128 + (k - 128);
            else              ap = node_emb + (size_t)i_e * 128 + (k - 256);
        } else {
            ap = Adense + (size_t)(m0 + ar) * C_DIM + k0 + aseg;
        }
        #pragma unroll
        for (int q = 0; q < 4; q++) fA[q] = reinterpret_cast<const float4*>(ap)[q];
    };
    auto loadB = [&](int k0) {
        int nr = n0 + br;
        if (nr < Nw) {
            const uint4* bp = reinterpret_cast<const uint4*>(
                Bw + (size_t)nr * C_DIM + k0 + bseg);
            uB[0] = bp[0]; uB[1] = bp[1];
        } else {
            uB[0] = make_uint4(0, 0, 0, 0); uB[1] = make_uint4(0, 0, 0, 0);
        }
    };
    auto storeStage = [&](int buf) {
        __half2 h[8];
        #pragma unroll
        for (int q = 0; q < 4; q++) {
            h[2 * q]     = __floats2half2_rn(fA[q].x, fA[q].y);
            h[2 * q + 1] = __floats2half2_rn(fA[q].z, fA[q].w);
        }
        uint4 ua0 = make_uint4(*(uint32_t*)&h[0], *(uint32_t*)&h[1],
                               *(uint32_t*)&h[2], *(uint32_t*)&h[3]);
        uint4 ua1 = make_uint4(*(uint32_t*)&h[4], *(uint32_t*)&h[5],
                               *(uint32_t*)&h[6], *(uint32_t*)&h[7]);
        uint4* pa = reinterpret_cast<uint4*>(&sA[buf][ar * LDSX + aseg]);
        pa[0] = ua0; pa[1] = ua1;
        uint4* pb = reinterpret_cast<uint4*>(&sB[buf][br * LDSX + bseg]);
        pb[0] = uB[0]; pb[1] = uB[1];
    };

    // -------- compute mapping
    const int lane = tid & 31, warp = tid >> 5;
    const int wm = warp & 3, wn = warp >> 2;       // 4 x 2 warp grid
    const int g = lane >> 2, t4 = lane & 3;
    const int a_row = (lane & 7) + ((lane >> 3) & 1) * 8;
    const int a_ko  = (lane >> 4) * 8;
    const int b_row = (lane & 7) + ((lane >> 4) & 1) * 8;
    const int b_ko  = ((lane >> 3) & 1) * 8;

    float acc[2][8][4];
    #pragma unroll
    for (int i = 0; i < 2; i++)
        #pragma unroll
        for (int j = 0; j < 8; j++)
            #pragma unroll
            for (int q = 0; q < 4; q++) acc[i][j][q] = 0.f;

    if (TANH && tid < 128) sAvec[tid] = a_vec[n0 + tid];

    loadA(0); loadB(0); storeStage(0);
    __syncthreads();

    const int KSTEPS = C_DIM / KT;   // 12
    for (int s = 0; s < KSTEPS; ++s) {
        const int buf = s & 1;
        if (s + 1 < KSTEPS) { loadA((s + 1) * KT); loadB((s + 1) * KT); }

        #pragma unroll
        for (int ks = 0; ks < 2; ++ks) {
            const int ko = ks * 16;
            uint32_t af[2][4], bf[4][4];
            #pragma unroll
            for (int i = 0; i < 2; i++) {
                uint32_t ad = (uint32_t)__cvta_generic_to_shared(
                    &sA[buf][(wm * 32 + i * 16 + a_row) * LDSX + ko + a_ko]);
                ldsm4(af[i], ad);
            }
            #pragma unroll
            for (int p = 0; p < 4; p++) {
                uint32_t bd = (uint32_t)__cvta_generic_to_shared(
                    &sB[buf][(wn * 64 + p * 16 + b_row) * LDSX + ko + b_ko]);
                ldsm4(bf[p], bd);
            }
            #pragma unroll
            for (int i = 0; i < 2; i++)
                #pragma unroll
                for (int j = 0; j < 8; j++)
                    mma16816(acc[i][j], af[i],
                             bf[j >> 1][(j & 1) * 2], bf[j >> 1][(j & 1) * 2 + 1]);
        }
        if (s + 1 < KSTEPS) storeStage(buf ^ 1);
        __syncthreads();
    }

    // -------- epilogue
    float sc[2][2] = {{0.f, 0.f}, {0.f, 0.f}};   // score partials (i, row-half)
    #pragma unroll
    for (int i = 0; i < 2; i++) {
        #pragma unroll
        for (int j = 0; j < 8; j++) {
            const int r = m0 + wm * 32 + i * 16 + g;
            const int cl = wn * 64 + j * 8 + t4 * 2;   // col within block
            const int c = n0 + cl;
            if (TANH) {
                __half* C = (__half*)Cout;
                float v0 = tanh_fast(acc[i][j][0]);
                float v1 = tanh_fast(acc[i][j][1]);
                float v2 = tanh_fast(acc[i][j][2]);
                float v3 = tanh_fast(acc[i][j][3]);
                float a0 = sAvec[cl], a1 = sAvec[cl + 1];
                sc[i][0] = fmaf(v0, a0, fmaf(v1, a1, sc[i][0]));
                sc[i][1] = fmaf(v2, a0, fmaf(v3, a1, sc[i][1]));
                *reinterpret_cast<__half2*>(&C[(size_t)r * Nw + c]) =
                    __floats2half2_rn(v0, v1);
                *reinterpret_cast<__half2*>(&C[(size_t)(r + 8) * Nw + c]) =
                    __floats2half2_rn(v2, v3);
            } else {
                float* C = (float*)Cout;
                if (c < Nw)     C[(size_t)r * Nw + c]           = acc[i][j][0] + bias[c];
                if (c + 1 < Nw) C[(size_t)r * Nw + c + 1]       = acc[i][j][1] + bias[c + 1];
                if (c < Nw)     C[(size_t)(r + 8) * Nw + c]     = acc[i][j][2] + bias[c];
                if (c + 1 < Nw) C[(size_t)(r + 8) * Nw + c + 1] = acc[i][j][3] + bias[c + 1];
            }
        }
    }

    if (TANH) {
        // reduce score partials over the 4 lanes of each quad (same row)
        #pragma unroll
        for (int i = 0; i < 2; i++)
            #pragma unroll
            for (int rh = 0; rh < 2; rh++) {
                sc[i][rh] += __shfl_xor_sync(0xffffffffu, sc[i][rh], 1);
                sc[i][rh] += __shfl_xor_sync(0xffffffffu, sc[i][rh], 2);
            }
        if (t4 == 0) {
            #pragma unroll
            for (int i = 0; i < 2; i++)
                #pragma unroll
                for (int rh = 0; rh < 2; rh++)
                    sScore[wn][wm * 32 + i * 16 + g + rh * 8] = sc[i][rh];
        }
        __syncthreads();
        if (tid < 128)
            g_spart[(size_t)blockIdx.x * M1 + m0 + tid] =
                sScore[0][tid] + sScore[1][tid];
    }
}

// ---------------------------------------------------------------------------
// Attention v2: per-batch block. Sum 3 score partials, softmax over L, then a
// single streaming pass over h (no smem staging) for the weighted sum.
// ---------------------------------------------------------------------------
__global__ __launch_bounds__(256)
void attn_kernel(void) {
    __shared__ float s_w[L_DIM];
    __shared__ float red[8];
    const int b = blockIdx.x, tid = threadIdx.x;
    const int lane = tid & 31, warp = tid >> 5;

    float v = -1e30f;
    if (tid < L_DIM) {
        size_t m = (size_t)b * L_DIM + tid;
        v = g_spart[m] + g_spart[M1 + m] + g_spart[2 * (size_t)M1 + m];
    }
    // softmax over L
    float mx = v;
    #pragma unroll
    for (int o = 16; o; o >>= 1) mx = fmaxf(mx, __shfl_xor_sync(0xffffffffu, mx, o));
    if (lane == 0) red[warp] = mx;
    __syncthreads();
    if (tid == 0) {
        float t = red[0];
        #pragma unroll
        for (int i = 1; i < 8; i++) t = fmaxf(t, red[i]);
        red[0] = t;
    }
    __syncthreads();
    const float gmax = red[0];
    __syncthreads();
    float e = (tid < L_DIM) ? expf(v - gmax) : 0.f;
    float sm = e;
    #pragma unroll
    for (int o = 16; o; o >>= 1) sm += __shfl_xor_sync(0xffffffffu, sm, o);
    if (lane == 0) red[warp] = sm;
    __syncthreads();
    if (tid == 0) {
        float t = 0.f;
        #pragma unroll
        for (int i = 0; i < 8; i++) t += red[i];
        red[0] = t;
    }
    __syncthreads();
    const float inv = 1.0f / red[0];
    if (tid < L_DIM) s_w[tid] = e * inv;
    __syncthreads();

    // single streaming pass: cv[b,c] = sum_l w[l] * h[b,l,c]
    if (tid < C_DIM / 2) {
        const __half2* hb2 = reinterpret_cast<const __half2*>(
            g_h + (size_t)b * L_DIM * C_DIM);
        float ax = 0.f, ay = 0.f;
        #pragma unroll 4
        for (int l = 0; l < L_DIM; l++) {
            float w = s_w[l];
            float2 f = __half22float2(hb2[l * (C_DIM / 2) + tid]);
            ax = fmaf(w, f.x, ax);
            ay = fmaf(w, f.y, ay);
        }
        *reinterpret_cast<float2*>(&g_cv[b * C_DIM + 2 * tid]) =
            make_float2(ax, ay);
    }
}

// ---------------------------------------------------------------------------
extern "C" void kernel_launch(void* const* d_in, const int* in_sizes, int n_in,
                              void* d_out, int out_size) {
    const int*   starts   = (const int*)  d_in[0];
    const int*   paths    = (const int*)  d_in[1];
    const int*   ends     = (const int*)  d_in[2];
    const float* node_emb = (const float*)d_in[3];
    const float* path_emb = (const float*)d_in[4];
    const float* W_fc     = (const float*)d_in[5];
    const float* a_vec    = (const float*)d_in[6];
    const float* W_out    = (const float*)d_in[7];
    const float* b_out    = (const float*)d_in[8];

    __half *p_h, *p_wfc, *p_wout;
    float  *p_cv;
    cudaGetSymbolAddress((void**)&p_h,    g_h);
    cudaGetSymbolAddress((void**)&p_cv,   g_cv);
    cudaGetSymbolAddress((void**)&p_wfc,  g_wfc);
    cudaGetSymbolAddress((void**)&p_wout, g_wout);

    // 0) weight conversions to fp16
    f2h_kernel<<<(C_DIM * C_DIM / 4 + 255) / 256, 256>>>(W_fc, p_wfc, C_DIM * C_DIM / 4);
    f2h_kernel<<<(OUT_D * C_DIM / 4 + 255) / 256, 256>>>(W_out, p_wout, OUT_D * C_DIM / 4);

    // 1) h = tanh(gather(ctx) @ W_fc^T) -> fp16, plus per-n-block score partials
    mma_gemm<1, 1><<<dim3(C_DIM / 128, M1 / 128), 256>>>(
        nullptr, starts, paths, ends, node_emb, path_emb,
        p_wfc, nullptr, a_vec, (void*)p_h, C_DIM);

    // 2) softmax + attention pooling -> cv fp32 [1024 x 384] (single h pass)
    attn_kernel<<<B_DIM, 256>>>();

    // 3) out = cv @ W_out^T + b_out -> fp32 [1024 x 10000]
    mma_gemm<0, 0><<<dim3((OUT_D + 127) / 128, B_DIM / 128), 256>>>(
        p_cv, nullptr, nullptr, nullptr, nullptr, nullptr,
        p_wout, b_out, nullptr, d_out, OUT_D);
}